// round 17
// baseline (speedup 1.0000x reference)
#include <cuda_runtime.h>
#include <cuda_fp16.h>
#include <cstdint>

// Problem dims
#define BATCH    8192
#define DIM      128          // in_dim == out_dim
#define KTOT     384          // permuted K: k = (half*3+pw)*64 + (j&63)
#define NSTEP    24           // 6 chunks x 4 k16-steps
#define MTILE    64           // batch rows per CTA
#define THREADS  512          // 16 warps: 4 (m) x 4 (n)
#define NCTA     (BATCH / MTILE)   // 128 = one full wave

// fp16 coefficients (permuted K order): g_Bf[o*384 + c*64 + (j&63)]
__device__ __half g_Bf[DIM * KTOT];
__device__ float g_Bias[DIM];

// smem layout (144 KB, all resident, ONE wait + ONE barrier):
//   A: 6 chunks x Af[64][64]f16 8K @ c*8192           = 48 KB @ 0
//   B: 6 chunks x Bf[128][64]f16 16K @ 49152 + c*16384 = 96 KB
#define A_CHUNK_STRIDE 8192u
#define B_BASE         49152u
#define B_CHUNK_STRIDE 16384u
#define SMEM_TOTAL     147456

// ---------------- helpers ----------------
__device__ __forceinline__ uint32_t smem_u32(const void* p) {
    uint32_t a;
    asm("{ .reg .u64 t; cvta.to.shared.u64 t, %1; cvt.u32.u64 %0, t; }" : "=r"(a) : "l"(p));
    return a;
}
__device__ __forceinline__ uint32_t swz128(uint32_t off) { return off ^ ((off >> 3) & 0x70); }

#define CP_ASYNC16(dst_u32, src_ptr)                                              \
    asm volatile("{ .reg .u64 g; cvta.to.global.u64 g, %1;\n"                     \
                 "cp.async.cg.shared.global [%0], [g], 16; }"                     \
                 :: "r"(dst_u32), "l"(src_ptr) : "memory")
#define CP_COMMIT()  asm volatile("cp.async.commit_group;" ::: "memory")
#define CP_WAITG(n)  asm volatile("cp.async.wait_group %0;" :: "n"(n) : "memory")

#define LDSM4(r, addr)                                                            \
    asm volatile("ldmatrix.sync.aligned.m8n8.x4.shared.b16 {%0,%1,%2,%3}, [%4];"  \
                 : "=r"((r)[0]), "=r"((r)[1]), "=r"((r)[2]), "=r"((r)[3])         \
                 : "r"(addr))

#define MMA_F16(c, A, b0v, b1v)                                                   \
    asm volatile("mma.sync.aligned.m16n8k16.row.col.f32.f16.f16.f32 "             \
                 "{%0,%1,%2,%3}, {%4,%5,%6,%7}, {%8,%9}, {%0,%1,%2,%3};"          \
                 : "+f"((c)[0]), "+f"((c)[1]), "+f"((c)[2]), "+f"((c)[3])         \
                 : "r"((A)[0]), "r"((A)[1]), "r"((A)[2]), "r"((A)[3]),            \
                   "r"(b0v), "r"(b1v))

__device__ __forceinline__ uint32_t pack_half2(float a, float b) {
    __half2 h = __floats2half2_rn(a, b);
    return *reinterpret_cast<uint32_t*>(&h);
}

// ---------------- prep: coeff -> fp16 (permuted K), vectorized, + bias ----------------
// One thread per edge-PAIR. 8192 pairs over 32 CTAs x 256 threads.
__global__ void prep_kernel(const float* __restrict__ coeff) {
    asm volatile("griddepcontrol.launch_dependents;");

    const int tid = threadIdx.x;
    const int idx = blockIdx.x * 256 + tid;       // pair index [0, 8192)
    const int o  = idx >> 6;
    const int jp = idx & 63;                      // pair -> j = 2*jp
    const float4* cp = reinterpret_cast<const float4*>(coeff) + 2 * (size_t)idx;
    float4 c0 = cp[0];
    float4 c1 = cp[1];
    const int cbase = (jp >= 32) ? 3 : 0;
    const int joff  = (2 * jp) & 63;
    uint32_t* dst = reinterpret_cast<uint32_t*>(g_Bf + o * KTOT + joff);
    dst[(cbase + 0) * 32] = pack_half2(c0.y, c1.y);
    dst[(cbase + 1) * 32] = pack_half2(c0.z, c1.z);
    dst[(cbase + 2) * 32] = pack_half2(c0.w, c1.w);

    float s = c0.x + c1.x;
#pragma unroll
    for (int off = 16; off; off >>= 1)
        s += __shfl_xor_sync(0xffffffffu, s, off);
    __shared__ float ps[8];
    if ((tid & 31) == 0) ps[tid >> 5] = s;
    __syncthreads();
    if (tid < 4)
        g_Bias[blockIdx.x * 4 + tid] = ps[2 * tid] + ps[2 * tid + 1];
}

// ---------------- main kernel (R12 structure + R16 prologue ordering) ----------------
__global__ void __launch_bounds__(THREADS, 1)
kan_mma(const float* __restrict__ x, float* __restrict__ out) {
    extern __shared__ char smem[];
    const uint32_t sb = smem_u32(smem);
    const int tid  = threadIdx.x;
    const int lane = tid & 31;
    const int wid  = tid >> 5;
    const int b0   = blockIdx.x * MTILE;

    // warp tile (16 x 32): 4 m-warps x 4 n-warps
    const int m0 = (wid & 3) * 16;
    const int n0 = (wid >> 2) * 32;

    // ---- 1) x loads first (prep-independent DRAM pole) ----
    const int sr = tid >> 3;                      // 0..63
    const int sq = tid & 7;                       // 0..7
    const float4* xr = reinterpret_cast<const float4*>(x + (size_t)(b0 + sr) * DIM);
    float4 xv0 = xr[sq * 2];
    float4 xv1 = xr[sq * 2 + 1];
    float4 xv2 = xr[16 + sq * 2];
    float4 xv3 = xr[16 + sq * 2 + 1];

    // ---- 2) wait for prep writes (g_Bf / g_Bias) ----
    asm volatile("griddepcontrol.wait;" ::: "memory");

    // ---- 3) issue ALL B cp.async (single commit group, as in R12) ----
#pragma unroll
    for (int i = 0; i < 12; ++i) {
        int idx = tid + i * THREADS;              // 0..6143
        int cn = idx >> 10;                       // chunk 0..5
        int n = (idx >> 3) & 127, k8 = idx & 7;
        const __half* src = g_Bf + (size_t)n * KTOT + cn * 64 + k8 * 8;
        uint32_t dst = B_BASE + (uint32_t)cn * B_CHUNK_STRIDE
                     + swz128((uint32_t)(n * 128 + k8 * 16));
        CP_ASYNC16(sb + dst, src);
    }
    CP_COMMIT();

    // bias prefetch (overlaps with B flight)
    float2 bs[4];
#pragma unroll
    for (int nj = 0; nj < 4; ++nj)
        bs[nj] = *reinterpret_cast<const float2*>(g_Bias + n0 + nj * 8 + 2 * (lane & 3));

    // ---- 4) build A tile WHILE B is in flight ----
    {
        const uint32_t abase = swz128((uint32_t)(sr * 128 + sq * 16));
#pragma unroll
        for (int h = 0; h < 2; ++h) {
            float xb[8], w[8];
            {
                float4 v0 = h ? xv2 : xv0;
                float4 v1 = h ? xv3 : xv1;
                xb[0] = v0.x; xb[1] = v0.y; xb[2] = v0.z; xb[3] = v0.w;
                xb[4] = v1.x; xb[5] = v1.y; xb[6] = v1.z; xb[7] = v1.w;
            }
#pragma unroll
            for (int i = 0; i < 8; ++i) w[i] = xb[i];
#pragma unroll
            for (int pw = 0; pw < 3; ++pw) {
                uint4 pk = make_uint4(pack_half2(w[0], w[1]), pack_half2(w[2], w[3]),
                                      pack_half2(w[4], w[5]), pack_half2(w[6], w[7]));
                *reinterpret_cast<uint4*>(
                    smem + (uint32_t)(h * 3 + pw) * A_CHUNK_STRIDE + abase) = pk;
                if (pw < 2) {
#pragma unroll
                    for (int i = 0; i < 8; ++i) w[i] *= xb[i];
                }
            }
        }
    }

    // ---- 5) SINGLE wait + barrier, then flat 24-step pipelined mainloop ----
    CP_WAITG(0);
    __syncthreads();

    float acc[4][4];
#pragma unroll
    for (int nj = 0; nj < 4; ++nj)
#pragma unroll
        for (int i = 0; i < 4; ++i) acc[nj][i] = 0.f;

    const uint32_t a_row = (uint32_t)(m0 + (lane & 15));
    const uint32_t a_kb  = (uint32_t)((lane >> 4) * 16);
    const uint32_t b_row = (uint32_t)(n0 + (lane & 7) + ((lane >> 4) << 3));
    const uint32_t b_kb  = (uint32_t)(((lane >> 3) & 1) * 16);

    uint32_t af[3][4], bf[3][2][4];

    auto load_step = [&](int step, int s) {
        const uint32_t ab = (uint32_t)(step >> 2) * A_CHUNK_STRIDE;
        const uint32_t bb = B_BASE + (uint32_t)(step >> 2) * B_CHUNK_STRIDE;
        const int ks = step & 3;
        LDSM4(af[s], sb + ab + swz128(a_row * 128 + ks * 32 + a_kb));
#pragma unroll
        for (int ni = 0; ni < 2; ++ni) {
            uint32_t off = swz128((b_row + ni * 16) * 128 + ks * 32 + b_kb);
            LDSM4(bf[s][ni], sb + bb + off);
        }
    };
    auto mma_step = [&](int s) {
#pragma unroll
        for (int nj = 0; nj < 4; ++nj) {
            const int ni = nj >> 1, br = (nj & 1) * 2;
            MMA_F16(acc[nj], af[s], bf[s][ni][br], bf[s][ni][br + 1]);
        }
    };

    load_step(0, 0);
    load_step(1, 1);
#pragma unroll
    for (int step = 0; step < NSTEP; ++step) {
        if (step + 2 < NSTEP) load_step(step + 2, (step + 2) % 3);
        mma_step(step % 3);
    }

    // ---- 6) epilogue: bias + store ----
    const int r0 = b0 + m0 + (lane >> 2);
#pragma unroll
    for (int nj = 0; nj < 4; ++nj) {
        const int col = n0 + nj * 8 + 2 * (lane & 3);
        float2 v0 = make_float2(acc[nj][0] + bs[nj].x, acc[nj][1] + bs[nj].y);
        float2 v1 = make_float2(acc[nj][2] + bs[nj].x, acc[nj][3] + bs[nj].y);
        *reinterpret_cast<float2*>(out + (size_t)r0 * DIM + col)       = v0;
        *reinterpret_cast<float2*>(out + (size_t)(r0 + 8) * DIM + col) = v1;
    }
}

// ---------------- launch ----------------
extern "C" void kernel_launch(void* const* d_in, const int* in_sizes, int n_in,
                              void* d_out, int out_size) {
    const float* x     = (const float*)d_in[0];   // [8192, 128] fp32
    const float* coeff = (const float*)d_in[1];   // [16384, 4]  fp32
    float* out = (float*)d_out;                   // [8192, 128] fp32

    cudaFuncSetAttribute(kan_mma, cudaFuncAttributeMaxDynamicSharedMemorySize, SMEM_TOTAL);

    prep_kernel<<<32, 256>>>(coeff);

    // PDL: main may start while prep runs; griddepcontrol.wait orders g_Bf reads.
    cudaLaunchConfig_t cfg = {};
    cfg.gridDim  = dim3(NCTA, 1, 1);
    cfg.blockDim = dim3(THREADS, 1, 1);
    cfg.dynamicSmemBytes = SMEM_TOTAL;
    cfg.stream = 0;
    cudaLaunchAttribute attr[1];
    attr[0].id = cudaLaunchAttributeProgrammaticStreamSerialization;
    attr[0].val.programmaticStreamSerializationAllowed = 1;
    cfg.attrs = attr;
    cfg.numAttrs = 1;
    cudaLaunchKernelEx(&cfg, kan_mma, x, out);
}